// round 12
// baseline (speedup 1.0000x reference)
#include <cuda_runtime.h>
#include <cuda_bf16.h>
#include <mma.h>
#include <math.h>
#include <cstdint>

using namespace nvcuda;

// Problem constants
#define BT   16
#define CH   1024
#define HW   48
#define SP   24
#define SS   576
#define HD   72
#define BB   64
#define BLK  512
#define KTAY 8
#define JJ   16

// ---------------- scratch ----------------
__device__ __align__(128) float g_H2[BB*HD*CH];      // tf32-rounded H2
__device__ __align__(128) float g_xm[BB*CH];
__device__ __align__(128) float g_u [BB*CH];
__device__ __align__(128) float g_t [BB*JJ];         // atomically accumulated
__device__ __align__(128) float g_T [BB*HD*JJ];      // atomically accumulated
__device__ __align__(128) float g_R [BB*HD*JJ];
__device__ __align__(128) float g_M2[HD*HD];
__device__ __align__(128) float g_wv[HD];
__device__ __align__(128) float g_mw2[HD];
__device__ float g_mb2;
__device__ __align__(128) float g_G [HD*HD];
__device__ __align__(128) float g_hs[HD];
__device__ __align__(128) float g_a [SS];
__device__ __align__(128) float g_bsh[SS];
__device__ __align__(128) float g_W1r[80*SS];        // tf32-rounded w_in1, rows 72..79 = 0
__device__ __align__(128) float g_W2r[SS*HD];        // tf32-rounded w_out2

__device__ __forceinline__ float tf32r(float v) { return wmma::__float_to_tf32(v); }

// streaming 16B async copy (L2 only — keeps L1 for resident weights)
__device__ __forceinline__ void cp_async16cg(float* smem_dst, const float* gmem_src) {
    unsigned int sa = (unsigned int)__cvta_generic_to_shared(smem_dst);
    asm volatile("cp.async.cg.shared.global [%0], [%1], 16;" :: "r"(sa), "l"(gmem_src));
}

// ---------------- kz: zero accumulators ----------------
__global__ void kz() {
    int i0 = blockIdx.x*512 + threadIdx.x, stride = gridDim.x*512;
    for (int i = i0; i < BB*HD*JJ; i += stride) g_T[i] = 0.f;
    for (int i = i0; i < BB*JJ;    i += stride) g_t[i] = 0.f;
    for (int i = i0; i < HD*HD;    i += stride) g_G[i] = 0.f;
    for (int i = i0; i < HD;       i += stride) g_hs[i] = 0.f;
}

// ---------------- kpr: pre-round weights to tf32 (RN) ----------------
__global__ void kpr(const float* __restrict__ w1, const float* __restrict__ w2o) {
    int i0 = blockIdx.x*512 + threadIdx.x, stride = gridDim.x*512;
    for (int idx = i0; idx < 80*SS; idx += stride) {
        int o = idx / SS;
        g_W1r[idx] = (o < HD) ? tf32r(w1[idx]) : 0.f;
    }
    for (int idx = i0; idx < SS*HD; idx += stride)
        g_W2r[idx] = tf32r(w2o[idx]);
}

// ---------------- kp2 ----------------
__global__ void kp2(const float* __restrict__ w2i, const float* __restrict__ b2i) {
    int t = threadIdx.x;
    if (t < HD) {
        float a = 0.f;
        for (int s = 0; s < SS; s++) a += w2i[s*HD + t];
        g_mw2[t] = a * (1.f/SS);
    }
    if (t == 600) {
        float a = 0.f;
        for (int s = 0; s < SS; s++) a += b2i[s];
        g_mb2 = a * (1.f/SS);
    }
}

// ---------------- kp1 ----------------
__global__ void kp1(const float* __restrict__ w1o, const float* __restrict__ w2i,
                    const float* __restrict__ b2i) {
    int o = blockIdx.x, o2 = threadIdx.x;
    float acc = 0.f;
    for (int s = 0; s < SS; s++) acc = fmaf(w1o[o*SS + s], w2i[s*HD + o2], acc);
    g_M2[o*HD + o2] = acc;
    if (o2 == 0) {
        float a2 = 0.f;
        for (int s = 0; s < SS; s++) a2 = fmaf(w1o[o*SS + s], b2i[s], a2);
        g_wv[o] = a2;
    }
}

// ---------------- K1: H=relu(W1.Xg+b1) tf32 wmma; A direct from global (L1-hot) ----------------
// 256 threads / 8 warps; warp w owns n16 block w. K=576 in 12 chunks of 48.
// B (x tiles) double-buffered via cp.async.cg; A fragments loaded from g_W1r.
// Epilogue: xm/u, then warp-per-row T/t with register powers + shfl reduction.
__global__ __launch_bounds__(256, 4) void k1_mma(const float* __restrict__ x,
        const float* __restrict__ b1) {
    __shared__ __align__(16) float sm[13312];   // Bs0 128*52 | Bs1 128*52
    float* Cs = sm;                             // [80][136] alias after loop
    float* xs = sm + 10880;                     // [128]
    float* us = sm + 11008;                     // [128]
    int tid = threadIdx.x, w = tid >> 5, lane = tid & 31;
    int n0 = blockIdx.x << 7;
    int b = n0 >> 10, c0 = n0 & 1023;
    int chunk = b >> 4, bt = b & 15;
    int ty = (chunk >> 1) * SP, tx = (chunk & 1) * SP;
    const float* xb = x + (size_t)(bt*CH + c0) * 2304 + ty*48 + tx;

    wmma::fragment<wmma::accumulator,16,16,8,float> acc[5];
#pragma unroll
    for (int i = 0; i < 5; i++) wmma::fill_fragment(acc[i], 0.f);

    // prefetch B chunk 0 into Bs0
    for (int q = tid; q < 1536; q += 256) {
        int c = q/12, qs = q - c*12;
        int row = (qs >= 6) ? 1 : 0, sxx = (qs - row*6) * 4;
        cp_async16cg(&sm[c*52 + row*24 + sxx], xb + (size_t)c*2304 + row*48 + sxx);
    }
    asm volatile("cp.async.commit_group;");

    for (int kc = 0; kc < 12; ++kc) {
        float* Bs = (kc & 1) ? sm + 6656 : sm;
        __syncthreads();                 // mma(kc-1) done reading the buffer we overwrite
        if (kc < 11) {                   // prefetch B(kc+1)
            float* Bn = (kc & 1) ? sm : sm + 6656;
            int sy0 = (kc + 1) * 2;
            for (int q = tid; q < 1536; q += 256) {
                int c = q/12, qs = q - c*12;
                int row = (qs >= 6) ? 1 : 0, sxx = (qs - row*6) * 4;
                cp_async16cg(&Bn[c*52 + row*24 + sxx],
                             xb + (size_t)c*2304 + (sy0 + row)*48 + sxx);
            }
            asm volatile("cp.async.commit_group;");
            asm volatile("cp.async.wait_group 1;");   // B(kc) done, B(kc+1) in flight
        } else {
            asm volatile("cp.async.wait_group 0;");
        }
        __syncthreads();                 // B(kc) visible to all warps
        const float* Ag = g_W1r + kc*48;
#pragma unroll
        for (int k8 = 0; k8 < 6; ++k8) {
            wmma::fragment<wmma::matrix_b,16,16,8,wmma::precision::tf32,wmma::col_major> bf;
            wmma::load_matrix_sync(bf, Bs + (w*16)*52 + k8*8, 52);
#pragma unroll
            for (int e = 0; e < 4; e++) bf.x[e] = tf32r(bf.x[e]);
#pragma unroll
            for (int i = 0; i < 5; ++i) {
                wmma::fragment<wmma::matrix_a,16,16,8,wmma::precision::tf32,wmma::row_major> af;
                wmma::load_matrix_sync(af, Ag + (i*16)*SS + k8*8, SS);
                wmma::mma_sync(acc[i], af, bf, acc[i]);
            }
        }
    }
    __syncthreads();
#pragma unroll
    for (int i = 0; i < 5; ++i)
        wmma::store_matrix_sync(Cs + (i*16)*136 + w*16, acc[i], 136, wmma::mem_row_major);
    __syncthreads();
    // xm/u for these 128 channels
    if (tid < 128) {
        int c = tid;
        float a = g_mb2;
#pragma unroll 8
        for (int o = 0; o < HD; o++) {
            float h = fmaxf(Cs[o*136 + c] + __ldg(&b1[o]), 0.f);
            a = fmaf(g_mw2[o], h, a);
        }
        g_xm[b*CH + c0 + c] = a;
        float uu = expf(-a*a);
        g_u [b*CH + c0 + c] = uu;
        xs[c] = a; us[c] = uu;
    }
    __syncthreads();
    // warp-per-row T (o<72) and t (o==72, ones row): register powers + shfl reduce
    {
        float4 xm4 = *(float4*)&xs[lane << 2];
        float4 u4  = *(float4*)&us[lane << 2];
        int blk = c0 >> 9;
        for (int o = w; o < 73; o += 8) {
            float4 h4;
            if (o < HD) {
                float bias = __ldg(&b1[o]);
                h4 = *(float4*)&Cs[o*136 + (lane << 2)];
                h4.x = fmaxf(h4.x + bias, 0.f); h4.y = fmaxf(h4.y + bias, 0.f);
                h4.z = fmaxf(h4.z + bias, 0.f); h4.w = fmaxf(h4.w + bias, 0.f);
            } else {
                h4 = make_float4(1.f, 1.f, 1.f, 1.f);
            }
            float p0 = u4.x, p1 = u4.y, p2 = u4.z, p3 = u4.w;
            float a[KTAY];
#pragma unroll
            for (int k = 0; k < KTAY; k++) {
                a[k] = fmaf(p0, h4.x, fmaf(p1, h4.y, fmaf(p2, h4.z, p3*h4.w)));
                p0 *= xm4.x; p1 *= xm4.y; p2 *= xm4.z; p3 *= xm4.w;
            }
#pragma unroll
            for (int off = 16; off; off >>= 1)
#pragma unroll
                for (int k = 0; k < KTAY; k++)
                    a[k] += __shfl_xor_sync(0xffffffffu, a[k], off);
            if (lane == 0) {
                if (o < HD) {
#pragma unroll
                    for (int k = 0; k < KTAY; k++)
                        atomicAdd(&g_T[(b*HD + o)*JJ + blk*KTAY + k], a[k]);
                } else {
#pragma unroll
                    for (int k = 0; k < KTAY; k++)
                        atomicAdd(&g_t[(b*2 + blk)*KTAY + k], a[k]);
                }
            }
        }
    }
}

// ---------------- K5: R = M2.T + wv (x) t  (once per b) ----------------
__global__ __launch_bounds__(288) void k5_R() {
    int b = blockIdx.x, tid = threadIdx.x;
    __shared__ float Ts[HD*JJ];
    __shared__ float tb[JJ];
    for (int idx = tid; idx < HD*JJ; idx += 288) Ts[idx] = g_T[b*HD*JJ + idx];
    if (tid < JJ) tb[tid] = g_t[b*JJ + tid];
    __syncthreads();
    for (int idx = tid; idx < HD*JJ; idx += 288) {
        int o = idx / JJ, jj = idx - o*JJ;
        float acc = g_wv[o] * tb[jj];
#pragma unroll 8
        for (int o2 = 0; o2 < HD; o2++)
            acc = fmaf(g_M2[o*HD + o2], Ts[o2*JJ + jj], acc);
        g_R[b*HD*JJ + idx] = acc;
    }
}

// ---------------- K6: H2 from R (written tf32-rounded) ----------------
__global__ __launch_bounds__(512) void k6_H2(const float* __restrict__ b1o) {
    int b = blockIdx.y;
    int d = blockIdx.x * 512 + threadIdx.x;
    int blk = d >> 9;
    int tid = threadIdx.x;
    __shared__ float Rs[HD*JJ];
    __shared__ float tb[JJ];
    __shared__ float bo[HD];
    for (int idx = tid; idx < HD*JJ; idx += 512) Rs[idx] = g_R[b*HD*JJ + idx];
    if (tid < JJ) tb[tid] = g_t[b*JJ + tid];
    if (tid < HD) bo[tid] = b1o[tid];
    __syncthreads();
    float xm = g_xm[b*CH + d];
    float p[KTAY];
    p[0] = 1.f;
#pragma unroll
    for (int k = 1; k < KTAY; k++) p[k] = p[k-1] * (2.f * xm / (float)k);
    float denom = 0.f;
#pragma unroll
    for (int k = 0; k < KTAY; k++) denom = fmaf(p[k], tb[blk*KTAY + k], denom);
    float inv = 1.0f / denom;
    for (int o = 0; o < HD; o++) {
        float acc = 0.f;
#pragma unroll
        for (int k = 0; k < KTAY; k++) acc = fmaf(Rs[o*JJ + blk*KTAY + k], p[k], acc);
        g_H2[(size_t)(b*HD + o)*CH + d] = tf32r(fmaxf(fmaf(acc, inv, bo[o]), 0.f));
    }
}

// ---------------- K6g: Gram (on rounded H2 — matches actual GEMM inputs) ----------------
__global__ __launch_bounds__(288) void k6g() {
    int blk = blockIdx.x;
    int b = blk >> 1, c0 = (blk & 1) << 9;
    int tid = threadIdx.x;
    int i0 = (tid % 24) * 3, j0 = (tid / 24) * 6;
    __shared__ float Hs[HD][65];
    float acc[3][6];
#pragma unroll
    for (int i = 0; i < 3; i++)
#pragma unroll
        for (int j = 0; j < 6; j++) acc[i][j] = 0.f;
    float hs = 0.f;
    for (int cc0 = 0; cc0 < 512; cc0 += 64) {
        for (int idx = tid; idx < HD*64; idx += 288) {
            int o = idx >> 6, cc = idx & 63;
            Hs[o][cc] = g_H2[(size_t)(b*HD + o)*CH + c0 + cc0 + cc];
        }
        __syncthreads();
        if (tid < HD) {
#pragma unroll 16
            for (int cc = 0; cc < 64; cc++) hs += Hs[tid][cc];
        }
#pragma unroll 4
        for (int cc = 0; cc < 64; cc++) {
            float a0 = Hs[i0][cc], a1 = Hs[i0+1][cc], a2 = Hs[i0+2][cc];
#pragma unroll
            for (int jj = 0; jj < 6; ++jj) {
                float bv = Hs[j0+jj][cc];
                acc[0][jj] = fmaf(a0, bv, acc[0][jj]);
                acc[1][jj] = fmaf(a1, bv, acc[1][jj]);
                acc[2][jj] = fmaf(a2, bv, acc[2][jj]);
            }
        }
        __syncthreads();
    }
#pragma unroll
    for (int ii = 0; ii < 3; ii++)
#pragma unroll
        for (int jj = 0; jj < 6; jj++)
            atomicAdd(&g_G[(i0+ii)*HD + j0+jj], acc[ii][jj]);
    if (tid < HD) atomicAdd(&g_hs[tid], hs);
}

// ---------------- K8b: analytic BN stats (rounded w2o for consistency) ----------------
__global__ __launch_bounds__(128) void k8b(const float* __restrict__ b2o,
        const float* __restrict__ gamma, const float* __restrict__ beta) {
    int s = blockIdx.x, t = threadIdx.x;
    __shared__ float rq[128], rd[128];
    float q = 0.f, d = 0.f;
    if (t < HD) {
        float wt = g_W2r[s*HD + t];
        float v = 0.f;
        for (int o2 = 0; o2 < HD; ++o2)
            v = fmaf(g_G[t*HD + o2], g_W2r[s*HD + o2], v);
        q = wt * v;
        d = wt * g_hs[t];
    }
    rq[t] = q; rd[t] = d;
    __syncthreads();
    for (int st = 64; st > 0; st >>= 1) {
        if (t < st) { rq[t] += rq[t+st]; rd[t] += rd[t+st]; }
        __syncthreads();
    }
    if (t == 0) {
        const float N = (float)(BB*CH);
        float bias = b2o[s];
        float dot = rd[0];
        float mu = dot / N + bias;
        float esq = rq[0]/N + 2.f*bias*dot/N + bias*bias;
        float var = esq - mu*mu;
        float a = rsqrtf(var + 1e-5f) * gamma[s];
        g_a  [s] = 0.25f * a;
        g_bsh[s] = 0.25f * (beta[s] + a*(bias - mu));
    }
}

// ---------------- K7f: O = W2r.H2 (tf32) + BN + scatter + relu ----------------
// N=64 channels/block (grid 1024), 384 threads / 12 warps. A fragments straight
// from global g_W2r (L1-hot); Bs (H2) staged once via cp.async.cg; Os separate.
// Warp: mg=w>>1 m16 tile within the 96-row pass, ng=w&1 n32.
__global__ __launch_bounds__(384, 3) void k7f(const float* __restrict__ x,
        float* __restrict__ out) {
    __shared__ __align__(16) float Bs[HD*68];     // [o][c] pitch 68
    __shared__ __align__(16) float Os[64*100];    // [c][sl] pitch 100
    int tid = threadIdx.x, w = tid >> 5;
    int mg = w >> 1, ng = w & 1;
    int n0 = blockIdx.x << 6;
    int b = n0 >> 10, c0 = n0 & 1023;

    for (int q = tid; q < HD*16; q += 384) {
        int o = q >> 4, c4 = (q & 15) * 4;
        cp_async16cg(&Bs[o*68 + c4], g_H2 + (size_t)(b*HD + o)*CH + c0 + c4);
    }
    asm volatile("cp.async.commit_group;");
    asm volatile("cp.async.wait_group 0;");
    __syncthreads();

    int chunk = b >> 4, bt = b & 15;
    int ty = (chunk >> 1)*SP, tx = (chunk & 1)*SP;
    const float* xb = x   + (size_t)(bt*CH + c0)*2304 + ty*48 + tx;
    float*       ob = out + (size_t)(bt*CH + c0)*2304 + ty*48 + tx;

    for (int p = 0; p < 6; ++p) {
        wmma::fragment<wmma::accumulator,16,16,8,float> acc[2];
        wmma::fill_fragment(acc[0], 0.f);
        wmma::fill_fragment(acc[1], 0.f);
        const float* Ag = g_W2r + (size_t)(p*96 + mg*16)*HD;
#pragma unroll
        for (int k8 = 0; k8 < 9; ++k8) {
            wmma::fragment<wmma::matrix_b,16,16,8,wmma::precision::tf32,wmma::row_major> bf[2];
            wmma::load_matrix_sync(bf[0], Bs + (k8*8)*68 + ng*32,      68);
            wmma::load_matrix_sync(bf[1], Bs + (k8*8)*68 + ng*32 + 16, 68);
            wmma::fragment<wmma::matrix_a,16,16,8,wmma::precision::tf32,wmma::row_major> af;
            wmma::load_matrix_sync(af, Ag + k8*8, HD);
            wmma::mma_sync(acc[0], af, bf[0], acc[0]);
            wmma::mma_sync(acc[1], af, bf[1], acc[1]);
        }
        __syncthreads();   // scatter(p-1) done reading Os
#pragma unroll
        for (int cf = 0; cf < 2; ++cf)
            wmma::store_matrix_sync(Os + (ng*32 + cf*16)*100 + mg*16,
                                    acc[cf], 100, wmma::mem_col_major);
        __syncthreads();   // Os stores visible
        for (int idx = tid; idx < 1536; idx += 384) {
            int sx4 = idx % 6;
            int t2  = idx / 6;
            int syl = t2 & 3;
            int c   = t2 >> 2;
            int sl  = syl*24 + sx4*4;
            int s0  = p*96 + sl;
            float4 v  = *(float4*)&Os[c*100 + sl];
            float4 av = *(const float4*)&g_a[s0];
            float4 bv = *(const float4*)&g_bsh[s0];
            size_t ga = (size_t)c*2304 + (p*4 + syl)*48 + sx4*4;
            float4 xv = __ldcs((const float4*)(xb + ga));
            float4 r;
            r.x = fmaxf(xv.x + fmaf(v.x, av.x, bv.x), 0.f);
            r.y = fmaxf(xv.y + fmaf(v.y, av.y, bv.y), 0.f);
            r.z = fmaxf(xv.z + fmaf(v.z, av.z, bv.z), 0.f);
            r.w = fmaxf(xv.w + fmaf(v.w, av.w, bv.w), 0.f);
            __stcs((float4*)(ob + ga), r);
        }
    }
}

// ---------------- launch ----------------
extern "C" void kernel_launch(void* const* d_in, const int* in_sizes, int n_in,
                              void* d_out, int out_size) {
    (void)in_sizes; (void)n_in; (void)out_size;
    const float* x      = (const float*)d_in[0];
    const float* w_in1  = (const float*)d_in[1];
    const float* b_in1  = (const float*)d_in[2];
    const float* w_in2  = (const float*)d_in[3];
    const float* b_in2  = (const float*)d_in[4];
    const float* w_out1 = (const float*)d_in[5];
    const float* b_out1 = (const float*)d_in[6];
    const float* w_out2 = (const float*)d_in[7];
    const float* b_out2 = (const float*)d_in[8];
    const float* gamma  = (const float*)d_in[9];
    const float* beta   = (const float*)d_in[10];
    float* out = (float*)d_out;

    kz <<<64, 512>>>();                                  // 1
    kp2<<<1, 640>>>(w_in2, b_in2);                       // 2
    kpr<<<64, 512>>>(w_in1, w_out2);                     // 3
    k1_mma<<<(BB*CH)/128, 256>>>(x, b_in1);              // 4  <- profiled slot
    kp1<<<HD, HD>>>(w_out1, w_in2, b_in2);               // 5
    k5_R<<<BB, 288>>>();                                 // 6
    k6_H2<<<dim3(CH/512, BB), 512>>>(b_out1);            // 7
    k6g<<<BB*2, 288>>>();                                // 8
    k8b<<<SS, 128>>>(b_out2, gamma, beta);               // 9
    k7f<<<(BB*CH)/64, 384>>>(x, out);                    // 10
}

// round 13
// speedup vs baseline: 1.1907x; 1.1907x over previous
#include <cuda_runtime.h>
#include <cuda_bf16.h>
#include <mma.h>
#include <math.h>
#include <cstdint>

using namespace nvcuda;

// Problem constants
#define BT   16
#define CH   1024
#define HW   48
#define SP   24
#define SS   576
#define HD   72
#define BB   64
#define BLK  512
#define KTAY 8
#define JJ   16

// ---------------- scratch ----------------
__device__ __align__(128) float g_xm[BB*CH];
__device__ __align__(128) float g_t [BB*JJ];         // atomically accumulated
__device__ __align__(128) float g_T [BB*HD*JJ];      // atomically accumulated
__device__ __align__(128) float g_R [BB*HD*JJ];
__device__ __align__(128) float g_M2[HD*HD];
__device__ __align__(128) float g_wv[HD];
__device__ __align__(128) float g_mw2[HD];
__device__ float g_mb2;
__device__ __align__(128) float g_G [HD*HD];
__device__ __align__(128) float g_hs[HD];
__device__ __align__(128) float g_a [SS];
__device__ __align__(128) float g_bsh[SS];
__device__ __align__(128) float g_W1r[80*SS];        // tf32-rounded w_in1, rows 72..79 = 0
__device__ __align__(128) float g_W2r[SS*HD];        // tf32-rounded w_out2

__device__ __forceinline__ float tf32r(float v) { return wmma::__float_to_tf32(v); }

__device__ __forceinline__ void cp_async16(float* smem_dst, const float* gmem_src) {
    unsigned int sa = (unsigned int)__cvta_generic_to_shared(smem_dst);
    asm volatile("cp.async.ca.shared.global [%0], [%1], 16;" :: "r"(sa), "l"(gmem_src));
}

// ---------------- kz: zero accumulators ----------------
__global__ void kz() {
    int i0 = blockIdx.x*512 + threadIdx.x, stride = gridDim.x*512;
    for (int i = i0; i < BB*HD*JJ; i += stride) g_T[i] = 0.f;
    for (int i = i0; i < BB*JJ;    i += stride) g_t[i] = 0.f;
    for (int i = i0; i < HD*HD;    i += stride) g_G[i] = 0.f;
    for (int i = i0; i < HD;       i += stride) g_hs[i] = 0.f;
}

// ---------------- kpr: pre-round weights to tf32 (RN) ----------------
__global__ void kpr(const float* __restrict__ w1, const float* __restrict__ w2o) {
    int i0 = blockIdx.x*512 + threadIdx.x, stride = gridDim.x*512;
    for (int idx = i0; idx < 80*SS; idx += stride) {
        int o = idx / SS;
        g_W1r[idx] = (o < HD) ? tf32r(w1[idx]) : 0.f;
    }
    for (int idx = i0; idx < SS*HD; idx += stride)
        g_W2r[idx] = tf32r(w2o[idx]);
}

// ---------------- kp2 ----------------
__global__ void kp2(const float* __restrict__ w2i, const float* __restrict__ b2i) {
    int t = threadIdx.x;
    if (t < HD) {
        float a = 0.f;
        for (int s = 0; s < SS; s++) a += w2i[s*HD + t];
        g_mw2[t] = a * (1.f/SS);
    }
    if (t == 600) {
        float a = 0.f;
        for (int s = 0; s < SS; s++) a += b2i[s];
        g_mb2 = a * (1.f/SS);
    }
}

// ---------------- kp1 ----------------
__global__ void kp1(const float* __restrict__ w1o, const float* __restrict__ w2i,
                    const float* __restrict__ b2i) {
    int o = blockIdx.x, o2 = threadIdx.x;
    float acc = 0.f;
    for (int s = 0; s < SS; s++) acc = fmaf(w1o[o*SS + s], w2i[s*HD + o2], acc);
    g_M2[o*HD + o2] = acc;
    if (o2 == 0) {
        float a2 = 0.f;
        for (int s = 0; s < SS; s++) a2 = fmaf(w1o[o*SS + s], b2i[s], a2);
        g_wv[o] = a2;
    }
}

// ---------------- K1: H=relu(W1.Xg+b1) tf32 wmma, cp.async A+B, fused xm + T ----------------
// (round-10 structure: the 150us version)
__global__ __launch_bounds__(256, 3) void k1_mma(const float* __restrict__ x,
        const float* __restrict__ b1) {
    __shared__ __align__(16) float sm[17472];   // As 80*52 | Bs0 128*52 | Bs1 128*52
    float* As = sm;
    float* Cs = sm;                             // [80][136] alias after loop
    float* xs = sm + 10880;                     // [128]
    float* us = sm + 11008;                     // [128]
    int tid = threadIdx.x, w = tid >> 5, lane = tid & 31;
    int n0 = blockIdx.x << 7;
    int b = n0 >> 10, c0 = n0 & 1023;
    int chunk = b >> 4, bt = b & 15;
    int ty = (chunk >> 1) * SP, tx = (chunk & 1) * SP;
    const float* xb = x + (size_t)(bt*CH + c0) * 2304 + ty*48 + tx;

    wmma::fragment<wmma::accumulator,16,16,8,float> acc[5];
#pragma unroll
    for (int i = 0; i < 5; i++) wmma::fill_fragment(acc[i], 0.f);

    // prefetch B chunk 0
    {
        float* Bn = sm + 4160;
        for (int q = tid; q < 1536; q += 256) {
            int c = q/12, qs = q - c*12;
            int row = (qs >= 6) ? 1 : 0, sxx = (qs - row*6) * 4;
            cp_async16(&Bn[c*52 + row*24 + sxx], xb + (size_t)c*2304 + row*48 + sxx);
        }
        asm volatile("cp.async.commit_group;");
    }

    for (int kc = 0; kc < 12; ++kc) {
        float* Bs = (kc & 1) ? sm + 10816 : sm + 4160;
        __syncthreads();                 // prior mma done reading As / Bn region
        // stage A(kc) via cp.async (pre-rounded, L2-hot)
        for (int q = tid; q < 960; q += 256) {
            int o = q/12, k4 = (q - o*12) * 4;
            cp_async16(&As[o*52 + k4], g_W1r + o*SS + kc*48 + k4);
        }
        asm volatile("cp.async.commit_group;");
        if (kc < 11) {                   // prefetch B(kc+1)
            float* Bn = (kc & 1) ? sm + 4160 : sm + 10816;
            int sy0 = (kc + 1) * 2;
            for (int q = tid; q < 1536; q += 256) {
                int c = q/12, qs = q - c*12;
                int row = (qs >= 6) ? 1 : 0, sxx = (qs - row*6) * 4;
                cp_async16(&Bn[c*52 + row*24 + sxx],
                           xb + (size_t)c*2304 + (sy0 + row)*48 + sxx);
            }
            asm volatile("cp.async.commit_group;");
            asm volatile("cp.async.wait_group 1;");   // B(kc)+A(kc) done, B(kc+1) in flight
        } else {
            asm volatile("cp.async.wait_group 0;");
        }
        __syncthreads();
#pragma unroll
        for (int k8 = 0; k8 < 6; ++k8) {
            wmma::fragment<wmma::matrix_b,16,16,8,wmma::precision::tf32,wmma::col_major> bf;
            wmma::load_matrix_sync(bf, Bs + (w*16)*52 + k8*8, 52);
#pragma unroll
            for (int e = 0; e < 4; e++) bf.x[e] = tf32r(bf.x[e]);
#pragma unroll
            for (int i = 0; i < 5; ++i) {
                wmma::fragment<wmma::matrix_a,16,16,8,wmma::precision::tf32,wmma::row_major> af;
                wmma::load_matrix_sync(af, As + (i*16)*52 + k8*8, 52);
                wmma::mma_sync(acc[i], af, bf, acc[i]);
            }
        }
    }
    __syncthreads();
#pragma unroll
    for (int i = 0; i < 5; ++i)
        wmma::store_matrix_sync(Cs + (i*16)*136 + w*16, acc[i], 136, wmma::mem_row_major);
    __syncthreads();
    // xm/u for these 128 channels
    if (tid < 128) {
        int c = tid;
        float a = g_mb2;
#pragma unroll 8
        for (int o = 0; o < HD; o++) {
            float h = fmaxf(Cs[o*136 + c] + __ldg(&b1[o]), 0.f);
            a = fmaf(g_mw2[o], h, a);
        }
        g_xm[b*CH + c0 + c] = a;
        xs[c] = a; us[c] = expf(-a*a);
    }
    __syncthreads();
    // warp-per-row T (o<72) and t (o==72, ones row): register powers + shfl reduce
    {
        float4 xm4 = *(float4*)&xs[lane << 2];
        float4 u4  = *(float4*)&us[lane << 2];
        int blk = c0 >> 9;
        for (int o = w; o < 73; o += 8) {
            float4 h4;
            if (o < HD) {
                float bias = __ldg(&b1[o]);
                h4 = *(float4*)&Cs[o*136 + (lane << 2)];
                h4.x = fmaxf(h4.x + bias, 0.f); h4.y = fmaxf(h4.y + bias, 0.f);
                h4.z = fmaxf(h4.z + bias, 0.f); h4.w = fmaxf(h4.w + bias, 0.f);
            } else {
                h4 = make_float4(1.f, 1.f, 1.f, 1.f);
            }
            float p0 = u4.x, p1 = u4.y, p2 = u4.z, p3 = u4.w;
            float a[KTAY];
#pragma unroll
            for (int k = 0; k < KTAY; k++) {
                a[k] = fmaf(p0, h4.x, fmaf(p1, h4.y, fmaf(p2, h4.z, p3*h4.w)));
                p0 *= xm4.x; p1 *= xm4.y; p2 *= xm4.z; p3 *= xm4.w;
            }
#pragma unroll
            for (int off = 16; off; off >>= 1)
#pragma unroll
                for (int k = 0; k < KTAY; k++)
                    a[k] += __shfl_xor_sync(0xffffffffu, a[k], off);
            if (lane == 0) {
                if (o < HD) {
#pragma unroll
                    for (int k = 0; k < KTAY; k++)
                        atomicAdd(&g_T[(b*HD + o)*JJ + blk*KTAY + k], a[k]);
                } else {
#pragma unroll
                    for (int k = 0; k < KTAY; k++)
                        atomicAdd(&g_t[(b*2 + blk)*KTAY + k], a[k]);
                }
            }
        }
    }
}

// ---------------- K5: R = M2.T + wv (x) t  (once per b) ----------------
__global__ __launch_bounds__(288) void k5_R() {
    int b = blockIdx.x, tid = threadIdx.x;
    __shared__ float Ts[HD*JJ];
    __shared__ float tb[JJ];
    for (int idx = tid; idx < HD*JJ; idx += 288) Ts[idx] = g_T[b*HD*JJ + idx];
    if (tid < JJ) tb[tid] = g_t[b*JJ + tid];
    __syncthreads();
    for (int idx = tid; idx < HD*JJ; idx += 288) {
        int o = idx / JJ, jj = idx - o*JJ;
        float acc = g_wv[o] * tb[jj];
#pragma unroll 8
        for (int o2 = 0; o2 < HD; o2++)
            acc = fmaf(g_M2[o*HD + o2], Ts[o2*JJ + jj], acc);
        g_R[b*HD*JJ + idx] = acc;
    }
}

// ---------------- K6g: Gram + hsum; H2 tile recomputed from R (no g_H2) ----------------
__global__ __launch_bounds__(288) void k6g(const float* __restrict__ b1o) {
    int gblk = blockIdx.x;
    int b = gblk >> 1, half = gblk & 1;
    int c0 = half << 9;
    int tid = threadIdx.x;
    int i0 = (tid % 24) * 3, j0 = (tid / 24) * 6;
    __shared__ float Hs[HD][65];
    __shared__ float Rs[HD*JJ];
    __shared__ float ps[KTAY][66];
    __shared__ float inv[64];
    __shared__ float tb[JJ];
    __shared__ float bo[HD];
    for (int idx = tid; idx < HD*JJ; idx += 288) Rs[idx] = g_R[b*HD*JJ + idx];
    if (tid < JJ) tb[tid] = g_t[b*JJ + tid];
    if (tid < HD) bo[tid] = b1o[tid];
    float acc[3][6];
#pragma unroll
    for (int i = 0; i < 3; i++)
#pragma unroll
        for (int j = 0; j < 6; j++) acc[i][j] = 0.f;
    float hsv = 0.f;
    for (int cc0 = 0; cc0 < 512; cc0 += 64) {
        __syncthreads();   // prev Hs/ps reads done; Rs/tb/bo ready (first iter)
        if (tid < 64) {
            float xm = g_xm[b*CH + c0 + cc0 + tid];
            float p = 1.f;
            ps[0][tid] = 1.f;
            float den = tb[half*KTAY];
            for (int k = 1; k < KTAY; k++) {
                p = p * (2.f * xm / (float)k);
                ps[k][tid] = p;
                den = fmaf(p, tb[half*KTAY + k], den);
            }
            inv[tid] = 1.f/den;
        }
        __syncthreads();
        for (int idx = tid; idx < HD*64; idx += 288) {
            int o = idx >> 6, cc = idx & 63;
            float a = 0.f;
            const float* rr = Rs + o*JJ + half*KTAY;
#pragma unroll
            for (int k = 0; k < KTAY; k++) a = fmaf(rr[k], ps[k][cc], a);
            Hs[o][cc] = tf32r(fmaxf(fmaf(a, inv[cc], bo[o]), 0.f));
        }
        __syncthreads();
        if (tid < HD) {
#pragma unroll 16
            for (int cc = 0; cc < 64; cc++) hsv += Hs[tid][cc];
        }
#pragma unroll 4
        for (int cc = 0; cc < 64; cc++) {
            float a0 = Hs[i0][cc], a1 = Hs[i0+1][cc], a2 = Hs[i0+2][cc];
#pragma unroll
            for (int jj = 0; jj < 6; ++jj) {
                float bv = Hs[j0+jj][cc];
                acc[0][jj] = fmaf(a0, bv, acc[0][jj]);
                acc[1][jj] = fmaf(a1, bv, acc[1][jj]);
                acc[2][jj] = fmaf(a2, bv, acc[2][jj]);
            }
        }
    }
#pragma unroll
    for (int ii = 0; ii < 3; ii++)
#pragma unroll
        for (int jj = 0; jj < 6; jj++)
            atomicAdd(&g_G[(i0+ii)*HD + j0+jj], acc[ii][jj]);
    if (tid < HD) atomicAdd(&g_hs[tid], hsv);
}

// ---------------- K8b: analytic BN stats (rounded w2o for consistency) ----------------
__global__ __launch_bounds__(128) void k8b(const float* __restrict__ b2o,
        const float* __restrict__ gamma, const float* __restrict__ beta) {
    int s = blockIdx.x, t = threadIdx.x;
    __shared__ float rq[128], rd[128];
    float q = 0.f, d = 0.f;
    if (t < HD) {
        float wt = g_W2r[s*HD + t];
        float v = 0.f;
        for (int o2 = 0; o2 < HD; ++o2)
            v = fmaf(g_G[t*HD + o2], g_W2r[s*HD + o2], v);
        q = wt * v;
        d = wt * g_hs[t];
    }
    rq[t] = q; rd[t] = d;
    __syncthreads();
    for (int st = 64; st > 0; st >>= 1) {
        if (t < st) { rq[t] += rq[t+st]; rd[t] += rd[t+st]; }
        __syncthreads();
    }
    if (t == 0) {
        const float N = (float)(BB*CH);
        float bias = b2o[s];
        float dot = rd[0];
        float mu = dot / N + bias;
        float esq = rq[0]/N + 2.f*bias*dot/N + bias*bias;
        float var = esq - mu*mu;
        float a = rsqrtf(var + 1e-5f) * gamma[s];
        g_a  [s] = 0.25f * a;
        g_bsh[s] = 0.25f * (beta[s] + a*(bias - mu));
    }
}

// ---------------- K7f: O = W2r.H2 (tf32) + BN + scatter + relu; H2 recomputed ----------------
// N=64 channels/block (grid 1024), 384 threads / 12 warps. Bs computed in-kernel
// from R (scratch aliased in Os); As (w2o) staged per pass overlapping scatter.
__global__ __launch_bounds__(384, 3) void k7f(const float* __restrict__ x,
        const float* __restrict__ b1o, float* __restrict__ out) {
    __shared__ __align__(16) float Bs[HD*68];     // [o][c] pitch 68
    __shared__ __align__(16) float As[96*76];     // [sl][o] pitch 76
    __shared__ __align__(16) float Os[6400];      // [c][sl] p100; prologue scratch alias
    float* Rs  = Os;            // 1152
    float* ps  = Os + 1152;     // 8*68
    float* inv = Os + 1696;     // 64
    float* tb  = Os + 1760;     // 16
    float* bo  = Os + 1776;     // 72
    int tid = threadIdx.x, w = tid >> 5;
    int mg = w >> 1, ng = w & 1;
    int n0 = blockIdx.x << 6;
    int b = n0 >> 10, c0 = n0 & 1023;
    int half = c0 >> 9;

    // stage As(0) early; overlaps the Bs computation below
    for (int q = tid; q < 96*18; q += 384) {
        int sl = q / 18, o4 = (q - sl*18) * 4;
        cp_async16(&As[sl*76 + o4], g_W2r + (size_t)sl*HD + o4);
    }
    asm volatile("cp.async.commit_group;");

    for (int idx = tid; idx < HD*JJ; idx += 384) Rs[idx] = g_R[b*HD*JJ + idx];
    if (tid < JJ) tb[tid] = g_t[b*JJ + tid];
    if (tid < HD) bo[tid] = b1o[tid];
    __syncthreads();
    if (tid < 64) {
        float xm = g_xm[b*CH + c0 + tid];
        float p = 1.f;
        ps[0*68 + tid] = 1.f;
        float den = tb[half*KTAY];
        for (int k = 1; k < KTAY; k++) {
            p = p * (2.f * xm / (float)k);
            ps[k*68 + tid] = p;
            den = fmaf(p, tb[half*KTAY + k], den);
        }
        inv[tid] = 1.f/den;
    }
    __syncthreads();
    for (int idx = tid; idx < HD*64; idx += 384) {
        int o = idx >> 6, c = idx & 63;
        float a = 0.f;
        const float* rr = Rs + o*JJ + half*KTAY;
#pragma unroll
        for (int k = 0; k < KTAY; k++) a = fmaf(rr[k], ps[k*68 + c], a);
        Bs[o*68 + c] = tf32r(fmaxf(fmaf(a, inv[c], bo[o]), 0.f));
    }
    asm volatile("cp.async.wait_group 0;");
    __syncthreads();   // Bs + As(0) ready; scratch region free for Os

    int chunk = b >> 4, bt = b & 15;
    int ty = (chunk >> 1)*SP, tx = (chunk & 1)*SP;
    const float* xb = x   + (size_t)(bt*CH + c0)*2304 + ty*48 + tx;
    float*       ob = out + (size_t)(bt*CH + c0)*2304 + ty*48 + tx;

    for (int p = 0; p < 6; ++p) {
        wmma::fragment<wmma::accumulator,16,16,8,float> acc[2];
        wmma::fill_fragment(acc[0], 0.f);
        wmma::fill_fragment(acc[1], 0.f);
#pragma unroll
        for (int k8 = 0; k8 < 9; ++k8) {
            wmma::fragment<wmma::matrix_b,16,16,8,wmma::precision::tf32,wmma::row_major> bf[2];
            wmma::load_matrix_sync(bf[0], Bs + (k8*8)*68 + ng*32,      68);
            wmma::load_matrix_sync(bf[1], Bs + (k8*8)*68 + ng*32 + 16, 68);
            wmma::fragment<wmma::matrix_a,16,16,8,wmma::precision::tf32,wmma::row_major> af;
            wmma::load_matrix_sync(af, As + (mg*16)*76 + k8*8, 76);
            wmma::mma_sync(acc[0], af, bf[0], acc[0]);
            wmma::mma_sync(acc[1], af, bf[1], acc[1]);
        }
        __syncthreads();   // mma done reading As; prev scatter done reading Os
#pragma unroll
        for (int cf = 0; cf < 2; ++cf)
            wmma::store_matrix_sync(Os + (ng*32 + cf*16)*100 + mg*16,
                                    acc[cf], 100, wmma::mem_col_major);
        if (p < 5) {       // stage As(p+1); overlaps the scatter below
            for (int q = tid; q < 96*18; q += 384) {
                int sl = q / 18, o4 = (q - sl*18) * 4;
                cp_async16(&As[sl*76 + o4], g_W2r + (size_t)((p+1)*96 + sl)*HD + o4);
            }
            asm volatile("cp.async.commit_group;");
        }
        __syncthreads();   // Os stores visible
        for (int idx = tid; idx < 1536; idx += 384) {
            int sx4 = idx % 6;
            int t2  = idx / 6;
            int syl = t2 & 3;
            int c   = t2 >> 2;
            int sl  = syl*24 + sx4*4;
            int s0  = p*96 + sl;
            float4 v  = *(float4*)&Os[c*100 + sl];
            float4 av = *(const float4*)&g_a[s0];
            float4 bv = *(const float4*)&g_bsh[s0];
            size_t ga = (size_t)c*2304 + (p*4 + syl)*48 + sx4*4;
            float4 xv = __ldcs((const float4*)(xb + ga));
            float4 r;
            r.x = fmaxf(xv.x + fmaf(v.x, av.x, bv.x), 0.f);
            r.y = fmaxf(xv.y + fmaf(v.y, av.y, bv.y), 0.f);
            r.z = fmaxf(xv.z + fmaf(v.z, av.z, bv.z), 0.f);
            r.w = fmaxf(xv.w + fmaf(v.w, av.w, bv.w), 0.f);
            __stcs((float4*)(ob + ga), r);
        }
        if (p < 5) {
            asm volatile("cp.async.wait_group 0;");
            __syncthreads();   // As(p+1) ready
        }
    }
}

// ---------------- launch ----------------
extern "C" void kernel_launch(void* const* d_in, const int* in_sizes, int n_in,
                              void* d_out, int out_size) {
    (void)in_sizes; (void)n_in; (void)out_size;
    const float* x      = (const float*)d_in[0];
    const float* w_in1  = (const float*)d_in[1];
    const float* b_in1  = (const float*)d_in[2];
    const float* w_in2  = (const float*)d_in[3];
    const float* b_in2  = (const float*)d_in[4];
    const float* w_out1 = (const float*)d_in[5];
    const float* b_out1 = (const float*)d_in[6];
    const float* w_out2 = (const float*)d_in[7];
    const float* b_out2 = (const float*)d_in[8];
    const float* gamma  = (const float*)d_in[9];
    const float* beta   = (const float*)d_in[10];
    float* out = (float*)d_out;

    kz <<<64, 512>>>();                                  // 1
    kp2<<<1, 640>>>(w_in2, b_in2);                       // 2
    kpr<<<64, 512>>>(w_in1, w_out2);                     // 3
    k1_mma<<<(BB*CH)/128, 256>>>(x, b_in1);              // 4  <- profiled slot
    kp1<<<HD, HD>>>(w_out1, w_in2, b_in2);               // 5
    k5_R<<<BB, 288>>>();                                 // 6
    k6g<<<BB*2, 288>>>(b_out1);                          // 7
    k8b<<<SS, 128>>>(b_out2, gamma, beta);               // 8
    k7f<<<(BB*CH)/64, 384>>>(x, b_out1, out);            // 9
}